// round 1
// baseline (speedup 1.0000x reference)
#include <cuda_runtime.h>
#include <cuda_bf16.h>
#include <math.h>

// ---------------------------------------------------------------------------
// PositionalEmbedding: out[n, d] = (x[n]==0 ? 0 : W[x[n], d]) + PE(n+1, d)
//   d odd : sin((n+1) * base^((d+1)/D))
//   d even: cos((n+1) * base^(d/D)),  base = fp32(1/10000)
// N=131072, D=1024, V=50257, fp32. HBM-bound (~1 GB traffic).
// ---------------------------------------------------------------------------

#define MAX_D 4096
__device__ float g_wtab[MAX_D];

// Kernel 1: w[j] = fp32( pow( (double)fp32(1e-4), (double)expo_j ) )
// Double-precision pow of the *fp32-rounded* base reproduces the reference's
// fp32 pow result (correctly rounded), avoiding pos-amplified w discrepancies.
__global__ void build_wtab_kernel(int D) {
    int j = blockIdx.x * blockDim.x + threadIdx.x;
    if (j >= D) return;
    float jf = (float)j;
    float Df = (float)D;
    float e = (j & 1) ? (jf + 1.0f) / Df : jf / Df;   // exact in fp32 (D=2^k)
    const double B = (double)(1.0f / 10000.0f);       // fp32-rounded base, as ref does
    g_wtab[j] = (float)pow(B, (double)e);
}

// Exact-ish argument reduction mod 2*pi via 3-term FMA Cody-Waite.
// ang in [0, 131072] -> q <= 20861 (< 2^15). C1 has 8 mantissa bits, so
// q*C1 is exact; FMAs round once each -> total reduction error ~5e-7 abs.
__device__ __forceinline__ float reduce_2pi(float ang) {
    const float INV2PI = 0.15915494309189535f;
    constexpr double TWO_PI = 6.28318530717958647692528676655900577;
    constexpr float C1 = 6.28125f;                                   // 8-bit mantissa
    constexpr float C2 = (float)(TWO_PI - (double)C1);
    constexpr float C3 = (float)(TWO_PI - (double)C1 - (double)((float)(TWO_PI - (double)C1)));
    float q = rintf(__fmul_rn(ang, INV2PI));
    float r = __fmaf_rn(-q, C1, ang);
    r = __fmaf_rn(-q, C2, r);
    r = __fmaf_rn(-q, C3, r);
    return r;   // in ~[-pi, pi]
}

__device__ __forceinline__ float pe_cos(float posf, float w) {
    float ang = __fmul_rn(posf, w);     // match reference fp32 product rounding
    return __cosf(reduce_2pi(ang));     // MUFU.COS, |err| <= 2^-21.4 on [-pi,pi]
}
__device__ __forceinline__ float pe_sin(float posf, float w) {
    float ang = __fmul_rn(posf, w);
    return __sinf(reduce_2pi(ang));
}

// Main kernel: one block per row, 256 threads (D=1024), one float4 per thread.
__global__ void __launch_bounds__(256) pos_emb_kernel(
    const int* __restrict__ x,
    const float* __restrict__ W,
    float* __restrict__ out,
    int D4)                             // D/4 (vec4 columns per row)
{
    int row = blockIdx.x;
    int t = threadIdx.x;
    if (t >= D4) return;

    int idx = __ldg(x + row);
    float posf = (float)(row + 1);      // pos <= 131072, exact in fp32

    const float4* wt4 = reinterpret_cast<const float4*>(g_wtab);
    float4 w4 = wt4[t];                 // 4 KB table: L1/L2 resident

    float4 e4 = make_float4(0.f, 0.f, 0.f, 0.f);
    if (idx != 0) {                     // padding_idx row is zero
        const float4* wrow = reinterpret_cast<const float4*>(W + (size_t)idx * (size_t)(D4 * 4));
        e4 = __ldg(wrow + t);           // LDG.128, coalesced 4KB row gather
    }

    float4 o;
    o.x = e4.x + pe_cos(posf, w4.x);    // j = 4t   (even -> cos)
    o.y = e4.y + pe_sin(posf, w4.y);    // j = 4t+1 (odd  -> sin)
    o.z = e4.z + pe_cos(posf, w4.z);    // j = 4t+2
    o.w = e4.w + pe_sin(posf, w4.w);    // j = 4t+3

    float4* out4 = reinterpret_cast<float4*>(out);
    out4[(size_t)row * (size_t)D4 + t] = o;   // STG.128, coalesced
}

extern "C" void kernel_launch(void* const* d_in, const int* in_sizes, int n_in,
                              void* d_out, int out_size) {
    // metadata order: x (int32, [N]), W (fp32, [V, D]). Defensive swap if needed.
    int xi = 0, wi = 1;
    if (n_in >= 2 && in_sizes[0] > in_sizes[1]) { xi = 1; wi = 0; }
    const int*   x = (const int*)d_in[xi];
    const float* W = (const float*)d_in[wi];
    float* out = (float*)d_out;

    int N = in_sizes[xi];
    int D = out_size / N;               // = 1024
    if (D > MAX_D) D = MAX_D;
    int D4 = D / 4;

    build_wtab_kernel<<<(D + 255) / 256, 256>>>(D);
    pos_emb_kernel<<<N, D4>>>(x, W, out, D4);
}

// round 5
// speedup vs baseline: 1.2290x; 1.2290x over previous
#include <cuda_runtime.h>
#include <cuda_bf16.h>
#include <math.h>

// ---------------------------------------------------------------------------
// PositionalEmbedding: out[n, d] = (x[n]==0 ? 0 : W[x[n], d]) + PE(n+1, d)
// N=131072, D=1024, V=50257, fp32. HBM-bound.
// R1 (measured): 194us @ 64% DRAM -- MLP=1 dependent gather + L2 pollution.
// R2-R4: 4 rows/block -> MLP=4 front-batched gathers; __stcs streaming
//        stores preserve W-table L2 residency. (R3/R4 were infra failures;
//        this design has not yet been measured.)
// ---------------------------------------------------------------------------

#define MAX_D 4096
__device__ float g_wtab[MAX_D];

// w[j] = fp32( pow( (double)fp32(1e-4), expo_j ) ) -- matches reference's
// fp32 pow bits (correctly rounded pow of the fp32-rounded base).
__global__ void build_wtab_kernel(int D) {
    int j = blockIdx.x * blockDim.x + threadIdx.x;
    if (j >= D) return;
    float jf = (float)j;
    float Df = (float)D;
    float e = (j & 1) ? (jf + 1.0f) / Df : jf / Df;   // exact (D = 2^k)
    const double B = (double)(1.0f / 10000.0f);
    g_wtab[j] = (float)pow(B, (double)e);
}

// 3-term FMA Cody-Waite reduction mod 2*pi. ang <= ~131072 -> q < 2^15;
// C1 has 8 mantissa bits so q*C1 exact; total reduction err ~5e-7 abs.
__device__ __forceinline__ float reduce_2pi(float ang) {
    const float INV2PI = 0.15915494309189535f;
    constexpr double TWO_PI = 6.28318530717958647692528676655900577;
    constexpr float C1 = 6.28125f;
    constexpr float C2 = (float)(TWO_PI - (double)C1);
    constexpr float C3 = (float)(TWO_PI - (double)C1 - (double)((float)(TWO_PI - (double)C1)));
    float q = rintf(__fmul_rn(ang, INV2PI));
    float r = __fmaf_rn(-q, C1, ang);
    r = __fmaf_rn(-q, C2, r);
    r = __fmaf_rn(-q, C3, r);
    return r;
}

__device__ __forceinline__ float pe_cos(float posf, float w) {
    return __cosf(reduce_2pi(__fmul_rn(posf, w)));    // MUFU.COS
}
__device__ __forceinline__ float pe_sin(float posf, float w) {
    return __sinf(reduce_2pi(__fmul_rn(posf, w)));    // MUFU.SIN
}

#define ROWS 4

// One block handles ROWS consecutive rows; thread t owns column group t.
// All ROWS gathers issued back-to-back (unconditional) -> MLP_p1 = ROWS.
__global__ void __launch_bounds__(256) pos_emb_kernel(
    const int* __restrict__ x,
    const float* __restrict__ W,
    float* __restrict__ out,
    int D4, int N)
{
    int t = threadIdx.x;
    if (t >= D4) return;
    int row0 = blockIdx.x * ROWS;       // always a multiple of ROWS (16B-aligned)

    // Block-uniform index load for the 4 rows (single LDG.128).
    int idx[ROWS];
    if (row0 + ROWS <= N) {
        int4 i4 = __ldg(reinterpret_cast<const int4*>(x + row0));
        idx[0] = i4.x; idx[1] = i4.y; idx[2] = i4.z; idx[3] = i4.w;
    } else {
#pragma unroll
        for (int r = 0; r < ROWS; r++) {
            int row = row0 + r;
            idx[r] = (row < N) ? __ldg(x + row) : 0;
        }
    }

    const float4* wt4 = reinterpret_cast<const float4*>(g_wtab);
    float4 w4 = wt4[t];                 // 4 KB table, L1-resident

    // Issue all gathers unconditionally (W[0] is valid memory; padding row
    // zero-selected afterwards). Keeps the LDG.128s front-batched -> MLP=4.
    float4 e[ROWS];
#pragma unroll
    for (int r = 0; r < ROWS; r++) {
        const float4* wrow = reinterpret_cast<const float4*>(W) + (size_t)idx[r] * (size_t)D4;
        e[r] = __ldg(wrow + t);
    }

    float4* out4 = reinterpret_cast<float4*>(out);
#pragma unroll
    for (int r = 0; r < ROWS; r++) {
        int row = row0 + r;
        if (row >= N) break;
        float posf = (float)(row + 1);
        float4 v = (idx[r] != 0) ? e[r] : make_float4(0.f, 0.f, 0.f, 0.f);
        float4 o;
        o.x = v.x + pe_cos(posf, w4.x); // j = 4t   (even -> cos)
        o.y = v.y + pe_sin(posf, w4.y); // j = 4t+1 (odd  -> sin)
        o.z = v.z + pe_cos(posf, w4.z); // j = 4t+2
        o.w = v.w + pe_sin(posf, w4.w); // j = 4t+3
        // Streaming store: output is write-once -> don't evict W from L2.
        __stcs(out4 + (size_t)row * (size_t)D4 + t, o);
    }
}

extern "C" void kernel_launch(void* const* d_in, const int* in_sizes, int n_in,
                              void* d_out, int out_size) {
    int xi = 0, wi = 1;
    if (n_in >= 2 && in_sizes[0] > in_sizes[1]) { xi = 1; wi = 0; }
    const int*   x = (const int*)d_in[xi];
    const float* W = (const float*)d_in[wi];
    float* out = (float*)d_out;

    int N = in_sizes[xi];
    int D = out_size / N;               // 1024
    if (D > MAX_D) D = MAX_D;
    int D4 = D / 4;

    build_wtab_kernel<<<(D + 255) / 256, 256>>>(D);
    int nblk = (N + ROWS - 1) / ROWS;
    pos_emb_kernel<<<nblk, D4>>>(x, W, out, D4, N);
}